// round 1
// baseline (speedup 1.0000x reference)
#include <cuda_runtime.h>
#include <cstddef>

#define T_STEPS  100
#define BATCH    256
#define IN_DIM   1024
#define HID      2048
#define OUT_DIM  10
#define DECAY    0.9f
#define THRESH   1.0f

// ---------------- device scratch (static, no allocations) ----------------
__device__ float g_X[(size_t)T_STEPS * BATCH * IN_DIM];   // transposed input: [T][B][IN_DIM]  (~104 MB)
__device__ float g_s1[BATCH * HID];
__device__ float g_s2[BATCH * HID];
__device__ float g_v1[BATCH * HID];
__device__ float g_v2[BATCH * HID];
__device__ float g_vout[BATCH * OUT_DIM];
__device__ float g_acc[BATCH * OUT_DIM];

// ---------------- transpose input_bins [B,IN_DIM,T] -> X [T, B*IN_DIM] ----------------
__global__ void transpose_kernel(const float* __restrict__ in)
{
    __shared__ float tile[32][33];
    int t0  = blockIdx.x * 32;
    int bi0 = blockIdx.y * 32;
    int tx = threadIdx.x;           // 0..31
    int ty = threadIdx.y;           // 0..7

    #pragma unroll
    for (int r = ty; r < 32; r += 8) {
        int bi = bi0 + r;
        int t  = t0 + tx;
        tile[r][tx] = (t < T_STEPS) ? in[(size_t)bi * T_STEPS + t] : 0.0f;
    }
    __syncthreads();
    #pragma unroll
    for (int r = ty; r < 32; r += 8) {
        int t  = t0 + r;
        int bi = bi0 + tx;
        if (t < T_STEPS)
            g_X[(size_t)t * (BATCH * IN_DIM) + bi] = tile[tx][r];
    }
}

// ---------------- zero persistent state ----------------
__global__ void zero_state_kernel()
{
    int i = blockIdx.x * 256 + threadIdx.x;
    if (i < BATCH * HID) { g_v1[i] = 0.0f; g_v2[i] = 0.0f; }
    if (i < BATCH * OUT_DIM) { g_vout[i] = 0.0f; g_acc[i] = 0.0f; }
}

// ---------------- fused GEMM (M=256 fixed) + LIF ----------------
// C[m][n] = sum_k A[m][k] * B[k][n];  then v = v*DECAY + C; spike = v>=1; v = spike?0:v
// CTA tile 64x64, 256 threads, 4x4 per thread, Kt = 16.
__global__ __launch_bounds__(256) void gemm_lif_kernel(
    const float* __restrict__ A, const float* __restrict__ B,
    float* __restrict__ v, float* __restrict__ s,
    int N, int K)
{
    __shared__ float As[64][16];   // [m][k]
    __shared__ float Bs[16][64];   // [k][n]

    int tid = threadIdx.x;
    int m0 = blockIdx.y * 64;
    int n0 = blockIdx.x * 64;
    int r = (tid >> 4) << 2;       // row offset within tile, 0..60
    int c = (tid & 15) << 2;       // col offset within tile, 0..60

    float acc[4][4] = {{0.f,0.f,0.f,0.f},{0.f,0.f,0.f,0.f},
                       {0.f,0.f,0.f,0.f},{0.f,0.f,0.f,0.f}};

    for (int k0 = 0; k0 < K; k0 += 16) {
        // load A tile: 64x16 = 1024 elems, 4 per thread
        #pragma unroll
        for (int e = 0; e < 4; e++) {
            int idx = tid + e * 256;
            int m = idx >> 4;
            int k = idx & 15;
            As[m][k] = A[(size_t)(m0 + m) * K + (k0 + k)];
        }
        // load B tile: 16x64 = 1024 elems, 4 per thread
        #pragma unroll
        for (int e = 0; e < 4; e++) {
            int idx = tid + e * 256;
            int k = idx >> 6;
            int n = idx & 63;
            Bs[k][n] = B[(size_t)(k0 + k) * N + (n0 + n)];
        }
        __syncthreads();

        #pragma unroll
        for (int k = 0; k < 16; k++) {
            float a0 = As[r + 0][k];
            float a1 = As[r + 1][k];
            float a2 = As[r + 2][k];
            float a3 = As[r + 3][k];
            float4 b4 = *(const float4*)&Bs[k][c];
            acc[0][0] += a0 * b4.x; acc[0][1] += a0 * b4.y; acc[0][2] += a0 * b4.z; acc[0][3] += a0 * b4.w;
            acc[1][0] += a1 * b4.x; acc[1][1] += a1 * b4.y; acc[1][2] += a1 * b4.z; acc[1][3] += a1 * b4.w;
            acc[2][0] += a2 * b4.x; acc[2][1] += a2 * b4.y; acc[2][2] += a2 * b4.z; acc[2][3] += a2 * b4.w;
            acc[3][0] += a3 * b4.x; acc[3][1] += a3 * b4.y; acc[3][2] += a3 * b4.z; acc[3][3] += a3 * b4.w;
        }
        __syncthreads();
    }

    // fused LIF epilogue
    #pragma unroll
    for (int i = 0; i < 4; i++) {
        size_t base = (size_t)(m0 + r + i) * N + (n0 + c);
        #pragma unroll
        for (int j = 0; j < 4; j++) {
            float vv = v[base + j] * DECAY + acc[i][j];
            bool sp = (vv >= THRESH);
            s[base + j] = sp ? 1.0f : 0.0f;
            v[base + j] = sp ? 0.0f : vv;
        }
    }
}

// ---------------- output layer: current = s2 @ W_ho, LIF, accumulate spike rate ----------------
__global__ __launch_bounds__(128) void out_layer_kernel(const float* __restrict__ W)
{
    int b = blockIdx.x;
    int tid = threadIdx.x;

    float acc[OUT_DIM];
    #pragma unroll
    for (int o = 0; o < OUT_DIM; o++) acc[o] = 0.0f;

    const float* srow = &g_s2[(size_t)b * HID];
    for (int i = tid; i < HID; i += 128) {
        float sv = srow[i];
        if (sv != 0.0f) {
            #pragma unroll
            for (int o = 0; o < OUT_DIM; o++)
                acc[o] += W[(size_t)i * OUT_DIM + o];
        }
    }

    __shared__ float red[OUT_DIM][128];
    #pragma unroll
    for (int o = 0; o < OUT_DIM; o++) red[o][tid] = acc[o];
    __syncthreads();

    for (int stride = 64; stride > 0; stride >>= 1) {
        if (tid < stride) {
            #pragma unroll
            for (int o = 0; o < OUT_DIM; o++)
                red[o][tid] += red[o][tid + stride];
        }
        __syncthreads();
    }

    if (tid < OUT_DIM) {
        float cur = red[tid][0];
        int idx = b * OUT_DIM + tid;
        float vv = g_vout[idx] * DECAY + cur;
        bool sp = (vv >= THRESH);
        g_vout[idx] = sp ? 0.0f : vv;
        if (sp) g_acc[idx] += 1.0f;
    }
}

// ---------------- finalize: rates = acc / T ----------------
__global__ void finalize_kernel(float* __restrict__ out)
{
    int i = blockIdx.x * 256 + threadIdx.x;
    if (i < BATCH * OUT_DIM) out[i] = g_acc[i] * (1.0f / T_STEPS);
}

// ---------------- launch ----------------
extern "C" void kernel_launch(void* const* d_in, const int* in_sizes, int n_in,
                              void* d_out, int out_size)
{
    const float* in_bins = (const float*)d_in[0];   // [256,1024,100]
    const float* W_ih    = (const float*)d_in[1];   // [1024,2048]
    const float* W_hh    = (const float*)d_in[2];   // [1,2048,2048]
    const float* W_ho    = (const float*)d_in[3];   // [2048,10]
    float* out = (float*)d_out;

    float *X, *s1, *s2, *v1, *v2;
    cudaGetSymbolAddress((void**)&X,  g_X);
    cudaGetSymbolAddress((void**)&s1, g_s1);
    cudaGetSymbolAddress((void**)&s2, g_s2);
    cudaGetSymbolAddress((void**)&v1, g_v1);
    cudaGetSymbolAddress((void**)&v2, g_v2);

    // 1) transpose input to [T][B*IN_DIM]
    {
        dim3 grid((T_STEPS + 31) / 32, (BATCH * IN_DIM) / 32);
        dim3 block(32, 8);
        transpose_kernel<<<grid, block>>>(in_bins);
    }
    // 2) zero persistent state
    zero_state_kernel<<<(BATCH * HID + 255) / 256, 256>>>();

    // 3) time loop
    dim3 g1(HID / 64, BATCH / 64);   // layer1: N=2048, M=256 -> 32x4 = 128 CTAs
    for (int t = 0; t < T_STEPS; t++) {
        const float* A0 = X + (size_t)t * BATCH * IN_DIM;
        gemm_lif_kernel<<<g1, 256>>>(A0, W_ih, v1, s1, HID, IN_DIM);
        gemm_lif_kernel<<<g1, 256>>>(s1, W_hh, v2, s2, HID, HID);
        out_layer_kernel<<<BATCH, 128>>>(W_ho);
    }

    // 4) finalize
    finalize_kernel<<<(BATCH * OUT_DIM + 255) / 256, 256>>>(out);
}

// round 2
// speedup vs baseline: 1.4816x; 1.4816x over previous
#include <cuda_runtime.h>
#include <cstddef>

#define T_STEPS  100
#define BATCH    256
#define IN_DIM   1024
#define HID      2048
#define OUT_DIM  10
#define DECAY    0.9f
#define THRESH   1.0f

// ---------------- device scratch (static, no allocations) ----------------
__device__ float g_X[(size_t)T_STEPS * BATCH * IN_DIM];   // transposed input: [T][B][IN_DIM]  (~104 MB)
__device__ float g_s1[BATCH * HID];
__device__ float g_s2[BATCH * HID];
__device__ float g_v1[BATCH * HID];
__device__ float g_v2[BATCH * HID];
__device__ float g_vout[BATCH * OUT_DIM];
__device__ float g_acc[BATCH * OUT_DIM];

// ---------------- transpose input_bins [B,IN_DIM,T] -> X [T, B*IN_DIM] ----------------
__global__ void transpose_kernel(const float* __restrict__ in)
{
    __shared__ float tile[32][33];
    int t0  = blockIdx.x * 32;
    int bi0 = blockIdx.y * 32;
    int tx = threadIdx.x;           // 0..31
    int ty = threadIdx.y;           // 0..7

    #pragma unroll
    for (int r = ty; r < 32; r += 8) {
        int bi = bi0 + r;
        int t  = t0 + tx;
        tile[r][tx] = (t < T_STEPS) ? in[(size_t)bi * T_STEPS + t] : 0.0f;
    }
    __syncthreads();
    #pragma unroll
    for (int r = ty; r < 32; r += 8) {
        int t  = t0 + r;
        int bi = bi0 + tx;
        if (t < T_STEPS)
            g_X[(size_t)t * (BATCH * IN_DIM) + bi] = tile[tx][r];
    }
}

// ---------------- zero persistent state ----------------
__global__ void zero_state_kernel()
{
    int i = blockIdx.x * 256 + threadIdx.x;
    if (i < BATCH * HID) { g_v1[i] = 0.0f; g_v2[i] = 0.0f; }
    if (i < BATCH * OUT_DIM) { g_vout[i] = 0.0f; g_acc[i] = 0.0f; }
}

// ---------------- fused GEMM (M=256 fixed) + LIF ----------------
// C[m][n] = sum_k A[m][k] * B[k][n];  then v = v*DECAY + C; spike = v>=1; v = spike?0:v
// CTA tile 64x64, 256 threads, 4x4 per thread, Kt = 16.
__global__ __launch_bounds__(256) void gemm_lif_kernel(
    const float* __restrict__ A, const float* __restrict__ B,
    float* __restrict__ v, float* __restrict__ s,
    int N, int K)
{
    __shared__ float As[64][16];   // [m][k]
    __shared__ float Bs[16][64];   // [k][n]

    int tid = threadIdx.x;
    int m0 = blockIdx.y * 64;
    int n0 = blockIdx.x * 64;
    int r = (tid >> 4) << 2;       // row offset within tile, 0..60
    int c = (tid & 15) << 2;       // col offset within tile, 0..60

    float acc[4][4] = {{0.f,0.f,0.f,0.f},{0.f,0.f,0.f,0.f},
                       {0.f,0.f,0.f,0.f},{0.f,0.f,0.f,0.f}};

    for (int k0 = 0; k0 < K; k0 += 16) {
        // load A tile: 64x16 = 1024 elems, 4 per thread
        #pragma unroll
        for (int e = 0; e < 4; e++) {
            int idx = tid + e * 256;
            int m = idx >> 4;
            int k = idx & 15;
            As[m][k] = A[(size_t)(m0 + m) * K + (k0 + k)];
        }
        // load B tile: 16x64 = 1024 elems, 4 per thread
        #pragma unroll
        for (int e = 0; e < 4; e++) {
            int idx = tid + e * 256;
            int k = idx >> 6;
            int n = idx & 63;
            Bs[k][n] = B[(size_t)(k0 + k) * N + (n0 + n)];
        }
        __syncthreads();

        #pragma unroll
        for (int k = 0; k < 16; k++) {
            float a0 = As[r + 0][k];
            float a1 = As[r + 1][k];
            float a2 = As[r + 2][k];
            float a3 = As[r + 3][k];
            float4 b4 = *(const float4*)&Bs[k][c];
            acc[0][0] += a0 * b4.x; acc[0][1] += a0 * b4.y; acc[0][2] += a0 * b4.z; acc[0][3] += a0 * b4.w;
            acc[1][0] += a1 * b4.x; acc[1][1] += a1 * b4.y; acc[1][2] += a1 * b4.z; acc[1][3] += a1 * b4.w;
            acc[2][0] += a2 * b4.x; acc[2][1] += a2 * b4.y; acc[2][2] += a2 * b4.z; acc[2][3] += a2 * b4.w;
            acc[3][0] += a3 * b4.x; acc[3][1] += a3 * b4.y; acc[3][2] += a3 * b4.z; acc[3][3] += a3 * b4.w;
        }
        __syncthreads();
    }

    // fused LIF epilogue
    #pragma unroll
    for (int i = 0; i < 4; i++) {
        size_t base = (size_t)(m0 + r + i) * N + (n0 + c);
        #pragma unroll
        for (int j = 0; j < 4; j++) {
            float vv = v[base + j] * DECAY + acc[i][j];
            bool sp = (vv >= THRESH);
            s[base + j] = sp ? 1.0f : 0.0f;
            v[base + j] = sp ? 0.0f : vv;
        }
    }
}

// ---------------- output layer: current = s2 @ W_ho, LIF, accumulate spike rate ----------------
__global__ __launch_bounds__(128) void out_layer_kernel(const float* __restrict__ W)
{
    int b = blockIdx.x;
    int tid = threadIdx.x;

    float acc[OUT_DIM];
    #pragma unroll
    for (int o = 0; o < OUT_DIM; o++) acc[o] = 0.0f;

    const float* srow = &g_s2[(size_t)b * HID];
    for (int i = tid; i < HID; i += 128) {
        float sv = srow[i];
        if (sv != 0.0f) {
            #pragma unroll
            for (int o = 0; o < OUT_DIM; o++)
                acc[o] += W[(size_t)i * OUT_DIM + o];
        }
    }

    __shared__ float red[OUT_DIM][128];
    #pragma unroll
    for (int o = 0; o < OUT_DIM; o++) red[o][tid] = acc[o];
    __syncthreads();

    for (int stride = 64; stride > 0; stride >>= 1) {
        if (tid < stride) {
            #pragma unroll
            for (int o = 0; o < OUT_DIM; o++)
                red[o][tid] += red[o][tid + stride];
        }
        __syncthreads();
    }

    if (tid < OUT_DIM) {
        float cur = red[tid][0];
        int idx = b * OUT_DIM + tid;
        float vv = g_vout[idx] * DECAY + cur;
        bool sp = (vv >= THRESH);
        g_vout[idx] = sp ? 0.0f : vv;
        if (sp) g_acc[idx] += 1.0f;
    }
}

// ---------------- finalize: rates = acc / T ----------------
__global__ void finalize_kernel(float* __restrict__ out)
{
    int i = blockIdx.x * 256 + threadIdx.x;
    if (i < BATCH * OUT_DIM) out[i] = g_acc[i] * (1.0f / T_STEPS);
}

// ---------------- launch ----------------
extern "C" void kernel_launch(void* const* d_in, const int* in_sizes, int n_in,
                              void* d_out, int out_size)
{
    const float* in_bins = (const float*)d_in[0];   // [256,1024,100]
    const float* W_ih    = (const float*)d_in[1];   // [1024,2048]
    const float* W_hh    = (const float*)d_in[2];   // [1,2048,2048]
    const float* W_ho    = (const float*)d_in[3];   // [2048,10]
    float* out = (float*)d_out;

    float *X, *s1, *s2, *v1, *v2;
    cudaGetSymbolAddress((void**)&X,  g_X);
    cudaGetSymbolAddress((void**)&s1, g_s1);
    cudaGetSymbolAddress((void**)&s2, g_s2);
    cudaGetSymbolAddress((void**)&v1, g_v1);
    cudaGetSymbolAddress((void**)&v2, g_v2);

    // 1) transpose input to [T][B*IN_DIM]
    {
        dim3 grid((T_STEPS + 31) / 32, (BATCH * IN_DIM) / 32);
        dim3 block(32, 8);
        transpose_kernel<<<grid, block>>>(in_bins);
    }
    // 2) zero persistent state
    zero_state_kernel<<<(BATCH * HID + 255) / 256, 256>>>();

    // 3) time loop
    dim3 g1(HID / 64, BATCH / 64);   // layer1: N=2048, M=256 -> 32x4 = 128 CTAs
    for (int t = 0; t < T_STEPS; t++) {
        const float* A0 = X + (size_t)t * BATCH * IN_DIM;
        gemm_lif_kernel<<<g1, 256>>>(A0, W_ih, v1, s1, HID, IN_DIM);
        gemm_lif_kernel<<<g1, 256>>>(s1, W_hh, v2, s2, HID, HID);
        out_layer_kernel<<<BATCH, 128>>>(W_ho);
    }

    // 4) finalize
    finalize_kernel<<<(BATCH * OUT_DIM + 255) / 256, 256>>>(out);
}

// round 7
// speedup vs baseline: 1.7112x; 1.1550x over previous
#include <cuda_runtime.h>
#include <cstddef>

#define T_STEPS  100
#define BATCH    256
#define IN_DIM   1024
#define HID      2048
#define OUT_DIM  10
#define DECAY    0.9f
#define THRESH   1.0f
#define CH       64          // k-elements per pipeline chunk

// ---------------- device scratch (static, no allocations) ----------------
__device__ float g_X[(size_t)T_STEPS * BATCH * IN_DIM];   // transposed input: [T][B][IN]
__device__ float g_s1[BATCH * HID];
__device__ float g_s2[BATCH * HID];
__device__ float g_v1[BATCH * HID];
__device__ float g_v2[BATCH * HID];
__device__ float g_vout[BATCH * OUT_DIM];
__device__ float g_acc[BATCH * OUT_DIM];

// ---------------- transpose input_bins [B,IN_DIM,T] -> X [T, B*IN_DIM] ----------------
__global__ void transpose_kernel(const float* __restrict__ in)
{
    __shared__ float tile[32][33];
    int t0  = blockIdx.x * 32;
    int bi0 = blockIdx.y * 32;
    int tx = threadIdx.x, ty = threadIdx.y;

    #pragma unroll
    for (int r = ty; r < 32; r += 8) {
        int bi = bi0 + r, t = t0 + tx;
        tile[r][tx] = (t < T_STEPS) ? in[(size_t)bi * T_STEPS + t] : 0.0f;
    }
    __syncthreads();
    #pragma unroll
    for (int r = ty; r < 32; r += 8) {
        int t = t0 + r, bi = bi0 + tx;
        if (t < T_STEPS)
            g_X[(size_t)t * (BATCH * IN_DIM) + bi] = tile[tx][r];
    }
}

__global__ void zero_state_kernel()
{
    int i = blockIdx.x * 256 + threadIdx.x;
    if (i < BATCH * HID) { g_v1[i] = 0.0f; g_v2[i] = 0.0f; }
    if (i < BATCH * OUT_DIM) { g_vout[i] = 0.0f; g_acc[i] = 0.0f; }
}

// ---------------- fp32 GEMM (M=256) + fused LIF ----------------
// C[m][n] = sum_k A[m][k]*B[k][n] with STRICT ascending-k single-accumulator FMA
// (bitwise identical to the validated R0 kernel). CTA tile 64x64, 256 threads,
// 4x4 per thread. A staged TRANSPOSED in smem (As[k][m]) so the inner loop is
// 2x LDS.128 + 16 FFMA. K-chunk 64 with register prefetch of the next chunk.
__global__ __launch_bounds__(256) void gemm_lif_kernel(
    const float* __restrict__ A, const float* __restrict__ B,
    float* __restrict__ v, float* __restrict__ s,
    int N, int K)
{
    __shared__ float As[CH][68];   // [k][m], padded
    __shared__ float Bs[CH][68];   // [k][n], padded

    int tid = threadIdx.x;
    int m0 = blockIdx.y * 64;
    int n0 = blockIdx.x * 64;
    int r = (tid >> 4) << 2;       // 0..60 step 4 (m offset)
    int c = (tid & 15) << 2;       // 0..60 step 4 (n offset)

    float acc[4][4] = {{0.f,0.f,0.f,0.f},{0.f,0.f,0.f,0.f},
                       {0.f,0.f,0.f,0.f},{0.f,0.f,0.f,0.f}};

    const int nch = K / CH;
    float4 aReg[4], bReg[4];

    // prefetch chunk 0 into registers
    #pragma unroll
    for (int e = 0; e < 4; e++) {
        int idx = tid + e * 256;
        int m  = idx >> 4, k4 = (idx & 15) << 2;
        aReg[e] = *(const float4*)&A[(size_t)(m0 + m) * K + k4];
        bReg[e] = *(const float4*)&B[(size_t)(idx >> 4) * N + n0 + ((idx & 15) << 2)];
    }
    // stage chunk 0 (A transposed)
    #pragma unroll
    for (int e = 0; e < 4; e++) {
        int idx = tid + e * 256;
        int m  = idx >> 4, k4 = (idx & 15) << 2;
        As[k4 + 0][m] = aReg[e].x;
        As[k4 + 1][m] = aReg[e].y;
        As[k4 + 2][m] = aReg[e].z;
        As[k4 + 3][m] = aReg[e].w;
        *(float4*)&Bs[idx >> 4][(idx & 15) << 2] = bReg[e];
    }
    __syncthreads();

    for (int ch = 0; ch < nch; ch++) {
        // issue next-chunk global loads (latency hidden under compute)
        if (ch + 1 < nch) {
            int k0 = (ch + 1) * CH;
            #pragma unroll
            for (int e = 0; e < 4; e++) {
                int idx = tid + e * 256;
                int m  = idx >> 4, k4 = (idx & 15) << 2;
                aReg[e] = *(const float4*)&A[(size_t)(m0 + m) * K + k0 + k4];
                bReg[e] = *(const float4*)&B[(size_t)(k0 + (idx >> 4)) * N + n0 + ((idx & 15) << 2)];
            }
        }

        // compute: ascending k, one FMA per k per output (order-identical to R0)
        #pragma unroll 16
        for (int k = 0; k < CH; k++) {
            float4 a4 = *(const float4*)&As[k][r];
            float4 b4 = *(const float4*)&Bs[k][c];
            acc[0][0] += a4.x * b4.x; acc[0][1] += a4.x * b4.y;
            acc[0][2] += a4.x * b4.z; acc[0][3] += a4.x * b4.w;
            acc[1][0] += a4.y * b4.x; acc[1][1] += a4.y * b4.y;
            acc[1][2] += a4.y * b4.z; acc[1][3] += a4.y * b4.w;
            acc[2][0] += a4.z * b4.x; acc[2][1] += a4.z * b4.y;
            acc[2][2] += a4.z * b4.z; acc[2][3] += a4.z * b4.w;
            acc[3][0] += a4.w * b4.x; acc[3][1] += a4.w * b4.y;
            acc[3][2] += a4.w * b4.z; acc[3][3] += a4.w * b4.w;
        }
        __syncthreads();

        if (ch + 1 < nch) {
            #pragma unroll
            for (int e = 0; e < 4; e++) {
                int idx = tid + e * 256;
                int m  = idx >> 4, k4 = (idx & 15) << 2;
                As[k4 + 0][m] = aReg[e].x;
                As[k4 + 1][m] = aReg[e].y;
                As[k4 + 2][m] = aReg[e].z;
                As[k4 + 3][m] = aReg[e].w;
                *(float4*)&Bs[idx >> 4][(idx & 15) << 2] = bReg[e];
            }
            __syncthreads();
        }
    }

    // fused LIF epilogue (elementwise; numerics identical to R0)
    #pragma unroll
    for (int i = 0; i < 4; i++) {
        size_t base = (size_t)(m0 + r + i) * N + (n0 + c);
        float4 vv = *(const float4*)&v[base];
        float t0 = vv.x * DECAY + acc[i][0];
        float t1 = vv.y * DECAY + acc[i][1];
        float t2 = vv.z * DECAY + acc[i][2];
        float t3 = vv.w * DECAY + acc[i][3];
        bool p0 = t0 >= THRESH, p1 = t1 >= THRESH, p2 = t2 >= THRESH, p3 = t3 >= THRESH;
        float4 vn, sn;
        vn.x = p0 ? 0.0f : t0; vn.y = p1 ? 0.0f : t1;
        vn.z = p2 ? 0.0f : t2; vn.w = p3 ? 0.0f : t3;
        sn.x = p0 ? 1.0f : 0.0f; sn.y = p1 ? 1.0f : 0.0f;
        sn.z = p2 ? 1.0f : 0.0f; sn.w = p3 ? 1.0f : 0.0f;
        *(float4*)&v[base] = vn;
        *(float4*)&s[base] = sn;
    }
}

// ---------------- output layer: current = s2 @ W_ho, LIF, accumulate spike rate ----------------
__global__ __launch_bounds__(128) void out_layer_kernel(const float* __restrict__ W)
{
    int b = blockIdx.x;
    int tid = threadIdx.x;

    float acc[OUT_DIM];
    #pragma unroll
    for (int o = 0; o < OUT_DIM; o++) acc[o] = 0.0f;

    const float* srow = &g_s2[(size_t)b * HID];
    for (int i = tid; i < HID; i += 128) {
        float sv = srow[i];
        if (sv != 0.0f) {
            #pragma unroll
            for (int o = 0; o < OUT_DIM; o++)
                acc[o] += W[(size_t)i * OUT_DIM + o];
        }
    }

    __shared__ float red[OUT_DIM][128];
    #pragma unroll
    for (int o = 0; o < OUT_DIM; o++) red[o][tid] = acc[o];
    __syncthreads();

    for (int stride = 64; stride > 0; stride >>= 1) {
        if (tid < stride) {
            #pragma unroll
            for (int o = 0; o < OUT_DIM; o++)
                red[o][tid] += red[o][tid + stride];
        }
        __syncthreads();
    }

    if (tid < OUT_DIM) {
        float cur = red[tid][0];
        int idx = b * OUT_DIM + tid;
        float vv = g_vout[idx] * DECAY + cur;
        bool sp = (vv >= THRESH);
        g_vout[idx] = sp ? 0.0f : vv;
        if (sp) g_acc[idx] += 1.0f;
    }
}

__global__ void finalize_kernel(float* __restrict__ out)
{
    int i = blockIdx.x * 256 + threadIdx.x;
    if (i < BATCH * OUT_DIM) out[i] = g_acc[i] * (1.0f / T_STEPS);
}

// ---------------- launch ----------------
extern "C" void kernel_launch(void* const* d_in, const int* in_sizes, int n_in,
                              void* d_out, int out_size)
{
    const float* in_bins = (const float*)d_in[0];   // [256,1024,100]
    const float* W_ih    = (const float*)d_in[1];   // [1024,2048]
    const float* W_hh    = (const float*)d_in[2];   // [1,2048,2048]
    const float* W_ho    = (const float*)d_in[3];   // [2048,10]
    float* out = (float*)d_out;

    float *X, *s1, *s2, *v1, *v2;
    cudaGetSymbolAddress((void**)&X,  g_X);
    cudaGetSymbolAddress((void**)&s1, g_s1);
    cudaGetSymbolAddress((void**)&s2, g_s2);
    cudaGetSymbolAddress((void**)&v1, g_v1);
    cudaGetSymbolAddress((void**)&v2, g_v2);

    // 1) transpose input to [T][B*IN_DIM]
    {
        dim3 grid((T_STEPS + 31) / 32, (BATCH * IN_DIM) / 32);
        transpose_kernel<<<grid, dim3(32, 8)>>>(in_bins);
    }
    // 2) zero persistent state
    zero_state_kernel<<<(BATCH * HID + 255) / 256, 256>>>();

    // 3) time loop
    dim3 gg(HID / 64, BATCH / 64);   // (32, 4) = 128 CTAs
    for (int t = 0; t < T_STEPS; t++) {
        const float* A0 = X + (size_t)t * BATCH * IN_DIM;
        gemm_lif_kernel<<<gg, 256>>>(A0, W_ih, v1, s1, HID, IN_DIM);
        gemm_lif_kernel<<<gg, 256>>>(s1, W_hh, v2, s2, HID, HID);
        out_layer_kernel<<<BATCH, 128>>>(W_ho);
    }

    // 4) finalize
    finalize_kernel<<<(BATCH * OUT_DIM + 255) / 256, 256>>>(out);
}

// round 8
// speedup vs baseline: 1.8332x; 1.0713x over previous
#include <cuda_runtime.h>
#include <cstddef>

#define T_STEPS  100
#define BATCH    256
#define IN_DIM   1024
#define HID      2048
#define OUT_DIM  10
#define DECAY    0.9f
#define THRESH   1.0f
#define CH       64          // k-elements per pipeline chunk

// ---------------- device scratch (static, no allocations) ----------------
__device__ float g_X[(size_t)T_STEPS * BATCH * IN_DIM];   // transposed input: [T][B][IN]
__device__ float g_s1[2 * BATCH * HID];                   // double-buffered layer1 spikes
__device__ float g_s2[2 * BATCH * HID];                   // double-buffered layer2 spikes
__device__ float g_v1[BATCH * HID];
__device__ float g_v2[BATCH * HID];
__device__ float g_vout[BATCH * OUT_DIM];
__device__ float g_acc[BATCH * OUT_DIM];

// ---------------- transpose input_bins [B,IN_DIM,T] -> X [T, B*IN_DIM] ----------------
__global__ void transpose_kernel(const float* __restrict__ in)
{
    __shared__ float tile[32][33];
    int t0  = blockIdx.x * 32;
    int bi0 = blockIdx.y * 32;
    int tx = threadIdx.x, ty = threadIdx.y;

    #pragma unroll
    for (int r = ty; r < 32; r += 8) {
        int bi = bi0 + r, t = t0 + tx;
        tile[r][tx] = (t < T_STEPS) ? in[(size_t)bi * T_STEPS + t] : 0.0f;
    }
    __syncthreads();
    #pragma unroll
    for (int r = ty; r < 32; r += 8) {
        int t = t0 + r, bi = bi0 + tx;
        if (t < T_STEPS)
            g_X[(size_t)t * (BATCH * IN_DIM) + bi] = tile[tx][r];
    }
}

__global__ void zero_state_kernel()
{
    int i = blockIdx.x * 256 + threadIdx.x;
    if (i < BATCH * HID) { g_v1[i] = 0.0f; g_v2[i] = 0.0f; }
    if (i < BATCH * OUT_DIM) { g_vout[i] = 0.0f; g_acc[i] = 0.0f; }
}

// ---------------- fp32 GEMM tile (64x64) + fused LIF  (numerics == R7, validated) ----------------
__device__ __forceinline__ void gemm_tile(
    const float* __restrict__ A, const float* __restrict__ B,
    float* __restrict__ v, float* __restrict__ s,
    int N, int K, int bx, int by, float* pool)
{
    float (*As)[68] = (float (*)[68])pool;            // [k][m], padded
    float (*Bs)[68] = (float (*)[68])(pool + CH * 68);// [k][n], padded

    int tid = threadIdx.x;
    int m0 = by * 64;
    int n0 = bx * 64;
    int r = (tid >> 4) << 2;       // 0..60 step 4 (m offset)
    int c = (tid & 15) << 2;       // 0..60 step 4 (n offset)

    float acc[4][4] = {{0.f,0.f,0.f,0.f},{0.f,0.f,0.f,0.f},
                       {0.f,0.f,0.f,0.f},{0.f,0.f,0.f,0.f}};

    const int nch = K / CH;
    float4 aReg[4], bReg[4];

    // prefetch chunk 0 into registers
    #pragma unroll
    for (int e = 0; e < 4; e++) {
        int idx = tid + e * 256;
        int m  = idx >> 4, k4 = (idx & 15) << 2;
        aReg[e] = *(const float4*)&A[(size_t)(m0 + m) * K + k4];
        bReg[e] = *(const float4*)&B[(size_t)(idx >> 4) * N + n0 + ((idx & 15) << 2)];
    }
    // stage chunk 0 (A transposed)
    #pragma unroll
    for (int e = 0; e < 4; e++) {
        int idx = tid + e * 256;
        int m  = idx >> 4, k4 = (idx & 15) << 2;
        As[k4 + 0][m] = aReg[e].x;
        As[k4 + 1][m] = aReg[e].y;
        As[k4 + 2][m] = aReg[e].z;
        As[k4 + 3][m] = aReg[e].w;
        *(float4*)&Bs[idx >> 4][(idx & 15) << 2] = bReg[e];
    }
    __syncthreads();

    for (int ch = 0; ch < nch; ch++) {
        // issue next-chunk global loads (latency hidden under compute)
        if (ch + 1 < nch) {
            int k0 = (ch + 1) * CH;
            #pragma unroll
            for (int e = 0; e < 4; e++) {
                int idx = tid + e * 256;
                int m  = idx >> 4, k4 = (idx & 15) << 2;
                aReg[e] = *(const float4*)&A[(size_t)(m0 + m) * K + k0 + k4];
                bReg[e] = *(const float4*)&B[(size_t)(k0 + (idx >> 4)) * N + n0 + ((idx & 15) << 2)];
            }
        }

        // compute: ascending k, one FMA per k per output (order-identical to R0/R7)
        #pragma unroll 16
        for (int k = 0; k < CH; k++) {
            float4 a4 = *(const float4*)&As[k][r];
            float4 b4 = *(const float4*)&Bs[k][c];
            acc[0][0] += a4.x * b4.x; acc[0][1] += a4.x * b4.y;
            acc[0][2] += a4.x * b4.z; acc[0][3] += a4.x * b4.w;
            acc[1][0] += a4.y * b4.x; acc[1][1] += a4.y * b4.y;
            acc[1][2] += a4.y * b4.z; acc[1][3] += a4.y * b4.w;
            acc[2][0] += a4.z * b4.x; acc[2][1] += a4.z * b4.y;
            acc[2][2] += a4.z * b4.z; acc[2][3] += a4.z * b4.w;
            acc[3][0] += a4.w * b4.x; acc[3][1] += a4.w * b4.y;
            acc[3][2] += a4.w * b4.z; acc[3][3] += a4.w * b4.w;
        }
        __syncthreads();

        if (ch + 1 < nch) {
            #pragma unroll
            for (int e = 0; e < 4; e++) {
                int idx = tid + e * 256;
                int m  = idx >> 4, k4 = (idx & 15) << 2;
                As[k4 + 0][m] = aReg[e].x;
                As[k4 + 1][m] = aReg[e].y;
                As[k4 + 2][m] = aReg[e].z;
                As[k4 + 3][m] = aReg[e].w;
                *(float4*)&Bs[idx >> 4][(idx & 15) << 2] = bReg[e];
            }
            __syncthreads();
        }
    }

    // fused LIF epilogue (elementwise; numerics identical to R7)
    #pragma unroll
    for (int i = 0; i < 4; i++) {
        size_t base = (size_t)(m0 + r + i) * N + (n0 + c);
        float4 vv = *(const float4*)&v[base];
        float t0 = vv.x * DECAY + acc[i][0];
        float t1 = vv.y * DECAY + acc[i][1];
        float t2 = vv.z * DECAY + acc[i][2];
        float t3 = vv.w * DECAY + acc[i][3];
        bool p0 = t0 >= THRESH, p1 = t1 >= THRESH, p2 = t2 >= THRESH, p3 = t3 >= THRESH;
        float4 vn, sn;
        vn.x = p0 ? 0.0f : t0; vn.y = p1 ? 0.0f : t1;
        vn.z = p2 ? 0.0f : t2; vn.w = p3 ? 0.0f : t3;
        sn.x = p0 ? 1.0f : 0.0f; sn.y = p1 ? 1.0f : 0.0f;
        sn.z = p2 ? 1.0f : 0.0f; sn.w = p3 ? 1.0f : 0.0f;
        *(float4*)&v[base] = vn;
        *(float4*)&s[base] = sn;
    }
}

// ---------------- fused step: blocks [0,128)=L2(t), [128,256)=L1(t+1), [256,384)=OUT(t-1) ----------------
__global__ __launch_bounds__(256) void fused_step_kernel(
    const float* __restrict__ Xt,     // L1 input for this call
    const float* __restrict__ W_ih,
    const float* __restrict__ W_hh,
    const float* __restrict__ W_ho,
    const float* __restrict__ s1r,    // L2 reads
    float* __restrict__ s1w,          // L1 writes
    const float* __restrict__ s2r,    // OUT reads
    float* __restrict__ s2w,          // L2 writes
    int doL1, int doL2, int doOUT)
{
    __shared__ float pool[2 * CH * 68];   // 34816 B; reused by OUT as reduction buffer
    int blk = blockIdx.x;
    int tid = threadIdx.x;

    if (blk < 128) {                       // ---- L2(t): s1r @ W_hh -> v2, s2w
        if (!doL2) return;
        gemm_tile(s1r, W_hh, g_v2, s2w, HID, HID, blk & 31, blk >> 5, pool);
    } else if (blk < 256) {                // ---- L1(t+1): Xt @ W_ih -> v1, s1w
        if (!doL1) return;
        int b2 = blk - 128;
        gemm_tile(Xt, W_ih, g_v1, s1w, HID, IN_DIM, b2 & 31, b2 >> 5, pool);
    } else {                               // ---- OUT(t-1): s2r @ W_ho, LIF, accumulate
        if (!doOUT) return;
        int group = tid >> 7;              // 0..1 (two 128-thread groups per block)
        int lt    = tid & 127;
        int b     = (blk - 256) * 2 + group;

        float accv[OUT_DIM];
        #pragma unroll
        for (int o = 0; o < OUT_DIM; o++) accv[o] = 0.0f;

        const float* srow = s2r + (size_t)b * HID;
        for (int i = lt; i < HID; i += 128) {
            float sv = srow[i];
            if (sv != 0.0f) {
                #pragma unroll
                for (int o = 0; o < OUT_DIM; o++)
                    accv[o] += W_ho[(size_t)i * OUT_DIM + o];
            }
        }

        float* red = pool;                 // [2][OUT_DIM][128]
        #pragma unroll
        for (int o = 0; o < OUT_DIM; o++) red[(group * OUT_DIM + o) * 128 + lt] = accv[o];
        __syncthreads();

        for (int stride = 64; stride > 0; stride >>= 1) {
            if (lt < stride) {
                #pragma unroll
                for (int o = 0; o < OUT_DIM; o++)
                    red[(group * OUT_DIM + o) * 128 + lt] +=
                        red[(group * OUT_DIM + o) * 128 + lt + stride];
            }
            __syncthreads();
        }

        if (lt < OUT_DIM) {
            float cur = red[(group * OUT_DIM + lt) * 128];
            int idx = b * OUT_DIM + lt;
            float vv = g_vout[idx] * DECAY + cur;
            bool sp = (vv >= THRESH);
            g_vout[idx] = sp ? 0.0f : vv;
            if (sp) g_acc[idx] += 1.0f;
        }
    }
}

__global__ void finalize_kernel(float* __restrict__ out)
{
    int i = blockIdx.x * 256 + threadIdx.x;
    if (i < BATCH * OUT_DIM) out[i] = g_acc[i] * (1.0f / T_STEPS);
}

// ---------------- launch ----------------
extern "C" void kernel_launch(void* const* d_in, const int* in_sizes, int n_in,
                              void* d_out, int out_size)
{
    const float* in_bins = (const float*)d_in[0];   // [256,1024,100]
    const float* W_ih    = (const float*)d_in[1];   // [1024,2048]
    const float* W_hh    = (const float*)d_in[2];   // [1,2048,2048]
    const float* W_ho    = (const float*)d_in[3];   // [2048,10]
    float* out = (float*)d_out;

    float *X, *s1, *s2;
    cudaGetSymbolAddress((void**)&X,  g_X);
    cudaGetSymbolAddress((void**)&s1, g_s1);
    cudaGetSymbolAddress((void**)&s2, g_s2);

    // 1) transpose input to [T][B*IN_DIM]
    {
        dim3 grid((T_STEPS + 31) / 32, (BATCH * IN_DIM) / 32);
        transpose_kernel<<<grid, dim3(32, 8)>>>(in_bins);
    }
    // 2) zero persistent state
    zero_state_kernel<<<(BATCH * HID + 255) / 256, 256>>>();

    // 3) software-pipelined time loop:
    //    call i runs L1(t=i), L2(t=i-1), OUT(t=i-2)
    for (int i = 0; i <= T_STEPS + 1; i++) {
        int ti = (i < T_STEPS) ? i : (T_STEPS - 1);
        const float* Xt  = X + (size_t)ti * BATCH * IN_DIM;
        float* s1w = s1 + (size_t)(i & 1) * BATCH * HID;
        const float* s1r = s1 + (size_t)((i - 1) & 1) * BATCH * HID;
        float* s2w = s2 + (size_t)((i - 1) & 1) * BATCH * HID;
        const float* s2r = s2 + (size_t)((i - 2) & 1) * BATCH * HID;
        int doL1  = (i < T_STEPS);
        int doL2  = (i >= 1) && (i <= T_STEPS);
        int doOUT = (i >= 2);
        fused_step_kernel<<<384, 256>>>(Xt, W_ih, W_hh, W_ho,
                                        s1r, s1w, s2r, s2w, doL1, doL2, doOUT);
    }

    // 4) finalize
    finalize_kernel<<<(BATCH * OUT_DIM + 255) / 256, 256>>>(out);
}

// round 9
// speedup vs baseline: 1.8508x; 1.0096x over previous
#include <cuda_runtime.h>
#include <cstdint>
#include <cstddef>

#define T_STEPS  100
#define BATCH    256
#define IN_DIM   1024
#define HID      2048
#define OUT_DIM  10
#define DECAY    0.9f
#define THRESH   1.0f
#define CH       32            // k-elements per chunk
#define AS_P     132           // As row pitch (floats): 128 + 4 pad
#define BS_P     68            // Bs row pitch (floats): 64 + 4 pad
#define STG_FL   (CH * AS_P + CH * BS_P)   // 6400 floats per stage
#define SMEM_BYTES (2 * STG_FL * 4)        // 51200 B

// ---------------- device scratch (static, no allocations) ----------------
__device__ float g_X[(size_t)T_STEPS * BATCH * IN_DIM];   // transposed input: [T][B][IN]
__device__ float g_s1[2 * BATCH * HID];
__device__ float g_s2[2 * BATCH * HID];
__device__ float g_v1[BATCH * HID];
__device__ float g_v2[BATCH * HID];
__device__ float g_vout[BATCH * OUT_DIM];
__device__ float g_acc[BATCH * OUT_DIM];

// ---------------- helpers ----------------
__device__ __forceinline__ uint32_t smem_u32(const void* p) {
    uint32_t a;
    asm("{ .reg .u64 t; cvta.to.shared.u64 t, %1; cvt.u32.u64 %0, t; }" : "=r"(a) : "l"(p));
    return a;
}
__device__ __forceinline__ void cp16(uint32_t dst, const void* src) {
    asm volatile("cp.async.cg.shared.global [%0], [%1], 16;" :: "r"(dst), "l"(src) : "memory");
}
#define CP_COMMIT() asm volatile("cp.async.commit_group;" ::: "memory")
#define CP_WAIT0()  asm volatile("cp.async.wait_group 0;" ::: "memory")

// ---------------- transpose input_bins [B,IN_DIM,T] -> X [T, B*IN_DIM] ----------------
__global__ void transpose_kernel(const float* __restrict__ in)
{
    __shared__ float tile[32][33];
    int t0  = blockIdx.x * 32;
    int bi0 = blockIdx.y * 32;
    int tx = threadIdx.x, ty = threadIdx.y;

    #pragma unroll
    for (int r = ty; r < 32; r += 8) {
        int bi = bi0 + r, t = t0 + tx;
        tile[r][tx] = (t < T_STEPS) ? in[(size_t)bi * T_STEPS + t] : 0.0f;
    }
    __syncthreads();
    #pragma unroll
    for (int r = ty; r < 32; r += 8) {
        int t = t0 + r, bi = bi0 + tx;
        if (t < T_STEPS)
            g_X[(size_t)t * (BATCH * IN_DIM) + bi] = tile[tx][r];
    }
}

__global__ void zero_state_kernel()
{
    int i = blockIdx.x * 256 + threadIdx.x;
    if (i < BATCH * HID) { g_v1[i] = 0.0f; g_v2[i] = 0.0f; }
    if (i < BATCH * OUT_DIM) { g_vout[i] = 0.0f; g_acc[i] = 0.0f; }
}

// ---------------- fp32 GEMM tile (128x64, 8x4/thread) + fused LIF ----------------
// Strict ascending-k single-accumulator FMA per output (bitwise == R7/R8, validated).
__device__ __forceinline__ void gemm_tile(
    const float* __restrict__ A, const float* __restrict__ B,
    float* __restrict__ v, float* __restrict__ s,
    int K, int bx, int by, float* pool)
{
    int tid = threadIdx.x;
    int m0 = by * 128;
    int n0 = bx * 64;

    // loader mapping
    int rA = tid >> 1;                 // 0..127  A row within tile
    int kA = (tid & 1) * 16;           // A k sub-base (16 floats per thread)
    int kB = tid >> 3;                 // 0..31   B k row
    int cB = (tid & 7) * 8;            // B col (8 floats)

    // compute mapping
    int r0 = (tid >> 4) << 2;          // 0..60
    int c  = (tid & 15) << 2;          // 0..60

    float acc[2][4][4];
    #pragma unroll
    for (int g = 0; g < 2; g++)
        #pragma unroll
        for (int i = 0; i < 4; i++)
            #pragma unroll
            for (int j = 0; j < 4; j++) acc[g][i][j] = 0.0f;

    const int nch = K / CH;
    float4 aReg[4];

    float* As[2] = { pool,            pool + STG_FL };
    float* Bs[2] = { pool + CH * AS_P, pool + STG_FL + CH * AS_P };
    uint32_t bsAddr[2] = { smem_u32(Bs[0]), smem_u32(Bs[1]) };

    // ---- stage chunk 0 into buffer 0 ----
    {
        const float* Ar = A + (size_t)(m0 + rA) * K + kA;
        #pragma unroll
        for (int e = 0; e < 4; e++) aReg[e] = *(const float4*)(Ar + e * 4);
        uint32_t bd = bsAddr[0] + (uint32_t)(kB * BS_P + cB) * 4;
        const float* Br = B + (size_t)kB * HID + n0 + cB;
        cp16(bd,      Br);
        cp16(bd + 16, Br + 4);
        CP_COMMIT();
        #pragma unroll
        for (int e = 0; e < 4; e++) {
            int kl = kA + e * 4;
            As[0][(kl + 0) * AS_P + rA] = aReg[e].x;
            As[0][(kl + 1) * AS_P + rA] = aReg[e].y;
            As[0][(kl + 2) * AS_P + rA] = aReg[e].z;
            As[0][(kl + 3) * AS_P + rA] = aReg[e].w;
        }
        CP_WAIT0();
    }
    __syncthreads();

    for (int ch = 0; ch < nch; ch++) {
        int b = ch & 1;
        const float* Asb = As[b];
        const float* Bsb = Bs[b];

        // issue next chunk loads (A->regs, B->smem via cp.async)
        if (ch + 1 < nch) {
            int k0 = (ch + 1) * CH;
            const float* Ar = A + (size_t)(m0 + rA) * K + k0 + kA;
            #pragma unroll
            for (int e = 0; e < 4; e++) aReg[e] = *(const float4*)(Ar + e * 4);
            uint32_t bd = bsAddr[b ^ 1] + (uint32_t)(kB * BS_P + cB) * 4;
            const float* Br = B + (size_t)(k0 + kB) * HID + n0 + cB;
            cp16(bd,      Br);
            cp16(bd + 16, Br + 4);
            CP_COMMIT();
        }

        // compute: ascending k, one FMA per k per output
        #pragma unroll 8
        for (int k = 0; k < CH; k++) {
            float4 a0 = *(const float4*)&Asb[k * AS_P + r0];
            float4 a1 = *(const float4*)&Asb[k * AS_P + r0 + 64];
            float4 b4 = *(const float4*)&Bsb[k * BS_P + c];
            acc[0][0][0] += a0.x * b4.x; acc[0][0][1] += a0.x * b4.y;
            acc[0][0][2] += a0.x * b4.z; acc[0][0][3] += a0.x * b4.w;
            acc[0][1][0] += a0.y * b4.x; acc[0][1][1] += a0.y * b4.y;
            acc[0][1][2] += a0.y * b4.z; acc[0][1][3] += a0.y * b4.w;
            acc[0][2][0] += a0.z * b4.x; acc[0][2][1] += a0.z * b4.y;
            acc[0][2][2] += a0.z * b4.z; acc[0][2][3] += a0.z * b4.w;
            acc[0][3][0] += a0.w * b4.x; acc[0][3][1] += a0.w * b4.y;
            acc[0][3][2] += a0.w * b4.z; acc[0][3][3] += a0.w * b4.w;
            acc[1][0][0] += a1.x * b4.x; acc[1][0][1] += a1.x * b4.y;
            acc[1][0][2] += a1.x * b4.z; acc[1][0][3] += a1.x * b4.w;
            acc[1][1][0] += a1.y * b4.x; acc[1][1][1] += a1.y * b4.y;
            acc[1][1][2] += a1.y * b4.z; acc[1][1][3] += a1.y * b4.w;
            acc[1][2][0] += a1.z * b4.x; acc[1][2][1] += a1.z * b4.y;
            acc[1][2][2] += a1.z * b4.z; acc[1][2][3] += a1.z * b4.w;
            acc[1][3][0] += a1.w * b4.x; acc[1][3][1] += a1.w * b4.y;
            acc[1][3][2] += a1.w * b4.z; acc[1][3][3] += a1.w * b4.w;
        }

        // stage A(next) + drain B(next) while other warps still compute
        if (ch + 1 < nch) {
            float* AsN = As[b ^ 1];
            #pragma unroll
            for (int e = 0; e < 4; e++) {
                int kl = kA + e * 4;
                AsN[(kl + 0) * AS_P + rA] = aReg[e].x;
                AsN[(kl + 1) * AS_P + rA] = aReg[e].y;
                AsN[(kl + 2) * AS_P + rA] = aReg[e].z;
                AsN[(kl + 3) * AS_P + rA] = aReg[e].w;
            }
            CP_WAIT0();
        }
        __syncthreads();
    }

    // fused LIF epilogue (numerics identical to R7/R8)
    #pragma unroll
    for (int g = 0; g < 2; g++) {
        #pragma unroll
        for (int i = 0; i < 4; i++) {
            size_t base = (size_t)(m0 + g * 64 + r0 + i) * HID + (n0 + c);
            float4 vv = *(const float4*)&v[base];
            float t0 = vv.x * DECAY + acc[g][i][0];
            float t1 = vv.y * DECAY + acc[g][i][1];
            float t2 = vv.z * DECAY + acc[g][i][2];
            float t3 = vv.w * DECAY + acc[g][i][3];
            bool p0 = t0 >= THRESH, p1 = t1 >= THRESH, p2 = t2 >= THRESH, p3 = t3 >= THRESH;
            float4 vn, sn;
            vn.x = p0 ? 0.0f : t0; vn.y = p1 ? 0.0f : t1;
            vn.z = p2 ? 0.0f : t2; vn.w = p3 ? 0.0f : t3;
            sn.x = p0 ? 1.0f : 0.0f; sn.y = p1 ? 1.0f : 0.0f;
            sn.z = p2 ? 1.0f : 0.0f; sn.w = p3 ? 1.0f : 0.0f;
            *(float4*)&v[base] = vn;
            *(float4*)&s[base] = sn;
        }
    }
}

// ---------------- fused step: [0,64)=L2(t), [64,128)=L1(t+1), [128,256)=OUT(t-1) ----------------
__global__ __launch_bounds__(256) void fused_step_kernel(
    const float* __restrict__ Xt,
    const float* __restrict__ W_ih,
    const float* __restrict__ W_hh,
    const float* __restrict__ W_ho,
    const float* __restrict__ s1r, float* __restrict__ s1w,
    const float* __restrict__ s2r, float* __restrict__ s2w,
    int doL1, int doL2, int doOUT)
{
    extern __shared__ float pool[];
    int blk = blockIdx.x;
    int tid = threadIdx.x;

    if (blk < 64) {                        // ---- L2(t)
        if (!doL2) return;
        gemm_tile(s1r, W_hh, g_v2, s2w, HID, blk & 31, blk >> 5, pool);
    } else if (blk < 128) {                // ---- L1(t+1)
        if (!doL1) return;
        int b2 = blk - 64;
        gemm_tile(Xt, W_ih, g_v1, s1w, IN_DIM, b2 & 31, b2 >> 5, pool);
    } else {                               // ---- OUT(t-1)  (identical to R8)
        if (!doOUT) return;
        int group = tid >> 7;
        int lt    = tid & 127;
        int b     = (blk - 128) * 2 + group;

        float accv[OUT_DIM];
        #pragma unroll
        for (int o = 0; o < OUT_DIM; o++) accv[o] = 0.0f;

        const float* srow = s2r + (size_t)b * HID;
        for (int i = lt; i < HID; i += 128) {
            float sv = srow[i];
            if (sv != 0.0f) {
                #pragma unroll
                for (int o = 0; o < OUT_DIM; o++)
                    accv[o] += W_ho[(size_t)i * OUT_DIM + o];
            }
        }

        float* red = pool;                 // [2][OUT_DIM][128]
        #pragma unroll
        for (int o = 0; o < OUT_DIM; o++) red[(group * OUT_DIM + o) * 128 + lt] = accv[o];
        __syncthreads();

        for (int stride = 64; stride > 0; stride >>= 1) {
            if (lt < stride) {
                #pragma unroll
                for (int o = 0; o < OUT_DIM; o++)
                    red[(group * OUT_DIM + o) * 128 + lt] +=
                        red[(group * OUT_DIM + o) * 128 + lt + stride];
            }
            __syncthreads();
        }

        if (lt < OUT_DIM) {
            float cur = red[(group * OUT_DIM + lt) * 128];
            int idx = b * OUT_DIM + lt;
            float vv = g_vout[idx] * DECAY + cur;
            bool sp = (vv >= THRESH);
            g_vout[idx] = sp ? 0.0f : vv;
            if (sp) g_acc[idx] += 1.0f;
        }
    }
}

__global__ void finalize_kernel(float* __restrict__ out)
{
    int i = blockIdx.x * 256 + threadIdx.x;
    if (i < BATCH * OUT_DIM) out[i] = g_acc[i] * (1.0f / T_STEPS);
}

// ---------------- launch ----------------
extern "C" void kernel_launch(void* const* d_in, const int* in_sizes, int n_in,
                              void* d_out, int out_size)
{
    const float* in_bins = (const float*)d_in[0];   // [256,1024,100]
    const float* W_ih    = (const float*)d_in[1];   // [1024,2048]
    const float* W_hh    = (const float*)d_in[2];   // [1,2048,2048]
    const float* W_ho    = (const float*)d_in[3];   // [2048,10]
    float* out = (float*)d_out;

    float *X, *s1, *s2;
    cudaGetSymbolAddress((void**)&X,  g_X);
    cudaGetSymbolAddress((void**)&s1, g_s1);
    cudaGetSymbolAddress((void**)&s2, g_s2);

    cudaFuncSetAttribute(fused_step_kernel,
                         cudaFuncAttributeMaxDynamicSharedMemorySize, SMEM_BYTES);

    // 1) transpose input
    {
        dim3 grid((T_STEPS + 31) / 32, (BATCH * IN_DIM) / 32);
        transpose_kernel<<<grid, dim3(32, 8)>>>(in_bins);
    }
    // 2) zero persistent state
    zero_state_kernel<<<(BATCH * HID + 255) / 256, 256>>>();

    // 3) software-pipelined time loop: call i runs L1(t=i), L2(t=i-1), OUT(t=i-2)
    for (int i = 0; i <= T_STEPS + 1; i++) {
        int ti = (i < T_STEPS) ? i : (T_STEPS - 1);
        const float* Xt  = X + (size_t)ti * BATCH * IN_DIM;
        float* s1w = s1 + (size_t)(i & 1) * BATCH * HID;
        const float* s1r = s1 + (size_t)((i - 1) & 1) * BATCH * HID;
        float* s2w = s2 + (size_t)((i - 1) & 1) * BATCH * HID;
        const float* s2r = s2 + (size_t)((i - 2) & 1) * BATCH * HID;
        int doL1  = (i < T_STEPS);
        int doL2  = (i >= 1) && (i <= T_STEPS);
        int doOUT = (i >= 2);
        fused_step_kernel<<<256, 256, SMEM_BYTES>>>(Xt, W_ih, W_hh, W_ho,
                                                    s1r, s1w, s2r, s2w,
                                                    doL1, doL2, doOUT);
    }

    // 4) finalize
    finalize_kernel<<<(BATCH * OUT_DIM + 255) / 256, 256>>>(out);
}